// round 1
// baseline (speedup 1.0000x reference)
#include <cuda_runtime.h>
#include <math.h>

// ---------------------------------------------------------------------------
// Problem constants
// ---------------------------------------------------------------------------
#define NN 64
#define CC 2048
#define HH 24
#define WW 12
#define PP 5
#define CLK 256          // local out channels per pose
#define HW  (HH*WW)      // 288
#define PC  (PP*CLK)     // 1280
#define CM  (CC+PC)      // 3328
#define KS  8            // split-K factor (both GEMMs)
#define BN_EPS 1e-5f

// ---------------------------------------------------------------------------
// Scratch (device globals; no allocation allowed)
// ---------------------------------------------------------------------------
__device__ float    g_inv_area[NN*PP];
__device__ unsigned g_maskbits[NN*HW];        // 5-bit in-box mask per (n, hw)
__device__ float    g_avg[PP*NN*CC];          // [p][n][c] pooled averages
__device__ float    g_cat[NN*CM];             // [n][1280 loc | 2048 gfeat]
__device__ float    g_lpart[KS*NN*PC];        // local GEMM split-K partials
__device__ float    g_mpart[KS*NN*CC];        // merge GEMM split-K partials

// ---------------------------------------------------------------------------
// Kernel 1: per-(n,p) box bounds + inv_area + per-(n,idx) 5-bit masks
// grid = 64 blocks, 288 threads
// ---------------------------------------------------------------------------
__global__ void boxes_masks_kernel(const float* __restrict__ poses)
{
    int n = blockIdx.x;
    __shared__ int s_box[PP][4];   // xs, xe, ys, ye
    int tid = threadIdx.x;
    if (tid < PP) {
        int p = tid;
        const float* kp = poses + ((long long)n*17 + p*4)*4;  // POSE_IDS = 4*p
        float kx = kp[0], ky = kp[1], kz = kp[2];
        float bx  = fminf(fmaxf(kx - 0.25f, 0.0f), 0.75f) * kz;
        float by  = fminf(fmaxf(ky - 0.25f, 0.0f), 0.75f) * kz;
        float bwh = 0.5f * kz;     // clip(0.5, 0, 0.75) == 0.5
        int xs = max(0,      (int)rintf((float)WW * bx));
        int xe = min(WW - 1, (int)rintf((float)WW * (bx + bwh)));
        int ys = max(0,      (int)rintf((float)HH * by));
        int ye = min(HH - 1, (int)rintf((float)HH * (by + bwh)));
        s_box[p][0] = xs; s_box[p][1] = xe; s_box[p][2] = ys; s_box[p][3] = ye;
        int area = (ye - ys) * (xe - xs);
        g_inv_area[n*PP + p] = (area > 0) ? (1.0f / (float)area) : 1.0f;
    }
    __syncthreads();
    int idx = tid;
    if (idx < HW) {
        int h = idx / WW, w = idx % WW;
        unsigned m = 0;
        #pragma unroll
        for (int p = 0; p < PP; ++p) {
            bool in = (h >= s_box[p][2]) && (h < s_box[p][3]) &&
                      (w >= s_box[p][0]) && (w < s_box[p][1]);
            if (in) m |= (1u << p);
        }
        g_maskbits[n*HW + idx] = m;
    }
}

// ---------------------------------------------------------------------------
// Kernel 2: fused box-average pooling + global max
// One block = (n, 256-channel tile). Stage x tiles via shared memory so the
// 5-bit mask lookups are uniform across the block (uniform predication, no
// divergence, no cross-lane reductions).
// grid = (8 ctiles, 64 n), 256 threads, static smem ~46 KB
// ---------------------------------------------------------------------------
#define CT 256           // channels per block
#define JT 36            // hw elements per stage (288/36 = 8 stages)
#define JP 44            // padded row stride (conflict-free LDS.128)

__global__ __launch_bounds__(256) void pool_kernel(const float* __restrict__ x)
{
    __shared__ float    s_x[CT*JP];
    __shared__ unsigned s_m[HW];
    __shared__ float    s_inv[PP];

    int n  = blockIdx.y;
    int c0 = blockIdx.x * CT;
    int tid = threadIdx.x;

    for (int i = tid; i < HW; i += 256) s_m[i] = g_maskbits[n*HW + i];
    if (tid < PP) s_inv[tid] = g_inv_area[n*PP + tid];

    const float* xb = x + ((long long)(n*CC + c0)) * HW;

    float s0 = 0.f, s1 = 0.f, s2 = 0.f, s3 = 0.f, s4 = 0.f;
    float gmax = -3.402823466e38f;

    #pragma unroll 1
    for (int stage = 0; stage < HW/JT; ++stage) {
        int j0 = stage * JT;
        __syncthreads();     // protects s_x (and s_m on stage 0)
        // stage: 256 rows x 36 floats = 2304 float4, 9 per thread, coalesced
        #pragma unroll
        for (int i = tid; i < CT*JT/4; i += 256) {
            int r  = i / (JT/4);
            int jj = i % (JT/4);
            float4 v = *(const float4*)(xb + (long long)r*HW + j0 + jj*4);
            *(float4*)&s_x[r*JP + jj*4] = v;
        }
        __syncthreads();
        // compute: thread owns channel row tid
        #pragma unroll
        for (int jj = 0; jj < JT; jj += 4) {
            float4 v = *(const float4*)&s_x[tid*JP + jj];
            float vv[4] = {v.x, v.y, v.z, v.w};
            #pragma unroll
            for (int e = 0; e < 4; ++e) {
                float val = vv[e];
                gmax = fmaxf(gmax, val);
                unsigned m = s_m[j0 + jj + e];   // uniform across block
                if (m & 1u)  s0 += val;
                if (m & 2u)  s1 += val;
                if (m & 4u)  s2 += val;
                if (m & 8u)  s3 += val;
                if (m & 16u) s4 += val;
            }
        }
    }

    int c = c0 + tid;
    g_avg[(0*NN + n)*CC + c] = s0 * s_inv[0];
    g_avg[(1*NN + n)*CC + c] = s1 * s_inv[1];
    g_avg[(2*NN + n)*CC + c] = s2 * s_inv[2];
    g_avg[(3*NN + n)*CC + c] = s3 * s_inv[3];
    g_avg[(4*NN + n)*CC + c] = s4 * s_inv[4];
    g_cat[n*CM + PC + c] = gmax;
}

// ---------------------------------------------------------------------------
// Kernel 3: split-K SGEMM  C[64, Ncols] = A[64, K] @ B[Ncols, K]^T
// MODE 0: local  (per-p: A = g_avg[p], B = local_w[p], K=2048, kchunk=256)
// MODE 1: merge  (A = g_cat, B = merge_w, K=3328, kchunk=416)
// 64x64 block tile, 4x4 micro-tile, 256 threads, partials to g_*part.
// grid: (ntiles, KS, z)  z = p for MODE 0, 1 for MODE 1
// ---------------------------------------------------------------------------
template<int MODE>
__global__ __launch_bounds__(256) void sgemm_splitk(const float* __restrict__ Bw)
{
    constexpr int LDA    = MODE ? CM   : CC;
    constexpr int LDB    = MODE ? CM   : CC;
    constexpr int NTOT   = MODE ? CC   : PC;
    constexpr int KCHUNK = MODE ? (CM/KS) : (CC/KS);   // 416 / 256

    int ntile = blockIdx.x;
    int ks    = blockIdx.y;
    int z     = blockIdx.z;

    const float* Ab = MODE ? g_cat : (g_avg + (long long)z * NN * CC);
    const float* Bb = Bw + (MODE ? 0 : (long long)z * CLK * CC)
                         + (long long)(ntile * 64) * LDB;
    float* Cp = MODE ? g_mpart : g_lpart;
    int colbase = (MODE ? 0 : z * CLK) + ntile * 64;

    __shared__ float As[16][64];
    __shared__ float Bs[16][64];

    int tid = threadIdx.x;
    int lr  = tid >> 2;            // 0..63 row for loading
    int lk4 = (tid & 3) * 4;       // 0,4,8,12 k offset
    int tx  = tid & 15;            // output col group
    int ty  = tid >> 4;            // output row group

    float acc[4][4];
    #pragma unroll
    for (int i = 0; i < 4; ++i)
        #pragma unroll
        for (int j = 0; j < 4; ++j) acc[i][j] = 0.f;

    int kbeg = ks * KCHUNK;
    for (int k0 = kbeg; k0 < kbeg + KCHUNK; k0 += 16) {
        float4 a4 = *(const float4*)(Ab + (long long)lr*LDA + k0 + lk4);
        float4 b4 = *(const float4*)(Bb + (long long)lr*LDB + k0 + lk4);
        As[lk4+0][lr] = a4.x; As[lk4+1][lr] = a4.y;
        As[lk4+2][lr] = a4.z; As[lk4+3][lr] = a4.w;
        Bs[lk4+0][lr] = b4.x; Bs[lk4+1][lr] = b4.y;
        Bs[lk4+2][lr] = b4.z; Bs[lk4+3][lr] = b4.w;
        __syncthreads();
        #pragma unroll
        for (int kk = 0; kk < 16; ++kk) {
            float4 av = *(const float4*)&As[kk][ty*4];
            float4 bv = *(const float4*)&Bs[kk][tx*4];
            float ar[4] = {av.x, av.y, av.z, av.w};
            float br[4] = {bv.x, bv.y, bv.z, bv.w};
            #pragma unroll
            for (int i = 0; i < 4; ++i)
                #pragma unroll
                for (int j = 0; j < 4; ++j)
                    acc[i][j] += ar[i] * br[j];
        }
        __syncthreads();
    }

    #pragma unroll
    for (int i = 0; i < 4; ++i) {
        float4 v = make_float4(acc[i][0], acc[i][1], acc[i][2], acc[i][3]);
        long long row = (long long)ks * NN + (ty*4 + i);
        *(float4*)(Cp + row * NTOT + colbase + tx*4) = v;
    }
}

// ---------------------------------------------------------------------------
// Kernel 4: local epilogue — reduce split-K, +bias, BN, ReLU -> g_cat[:, :1280]
// grid = 320 blocks x 256 threads  (64*1280 elements)
// ---------------------------------------------------------------------------
__global__ __launch_bounds__(256) void epi_local(
    const float* __restrict__ lb,   const float* __restrict__ lgam,
    const float* __restrict__ lbet, const float* __restrict__ lmean,
    const float* __restrict__ lvar)
{
    int e = blockIdx.x * 256 + threadIdx.x;     // < 64*1280
    int nrow = e / PC, col = e - nrow * PC;     // col = p*256 + k (matches flat (P,CL))
    float s = 0.f;
    #pragma unroll
    for (int ks = 0; ks < KS; ++ks)
        s += g_lpart[((long long)ks * NN + nrow) * PC + col];
    s += lb[col];
    float sc = lgam[col] * rsqrtf(lvar[col] + BN_EPS);
    s = (s - lmean[col]) * sc + lbet[col];
    g_cat[nrow*CM + col] = fmaxf(s, 0.f);
}

// ---------------------------------------------------------------------------
// Kernel 5: merge epilogue — reduce split-K, +bias, BN, ReLU, L2-normalize
// grid = 64 blocks (one per n) x 256 threads
// ---------------------------------------------------------------------------
__global__ __launch_bounds__(256) void epi_merge(
    const float* __restrict__ mb,   const float* __restrict__ mgam,
    const float* __restrict__ mbet, const float* __restrict__ mmean,
    const float* __restrict__ mvar, float* __restrict__ out)
{
    int nrow = blockIdx.x;
    int tid  = threadIdx.x;
    float yv[8];
    float ss = 0.f;
    #pragma unroll
    for (int i = 0; i < 8; ++i) {
        int c = tid + i*256;
        float s = 0.f;
        #pragma unroll
        for (int ks = 0; ks < KS; ++ks)
            s += g_mpart[((long long)ks * NN + nrow) * CC + c];
        s += mb[c];
        float sc = mgam[c] * rsqrtf(mvar[c] + BN_EPS);
        s = (s - mmean[c]) * sc + mbet[c];
        s = fmaxf(s, 0.f);
        yv[i] = s;
        ss += s * s;
    }
    __shared__ float red[256];
    red[tid] = ss;
    __syncthreads();
    #pragma unroll
    for (int o = 128; o > 0; o >>= 1) {
        if (tid < o) red[tid] += red[tid + o];
        __syncthreads();
    }
    float inv = 1.0f / fmaxf(sqrtf(red[0]), 1e-12f);
    #pragma unroll
    for (int i = 0; i < 8; ++i)
        out[(long long)nrow*CC + tid + i*256] = yv[i] * inv;
}

// ---------------------------------------------------------------------------
// Launch
// ---------------------------------------------------------------------------
extern "C" void kernel_launch(void* const* d_in, const int* in_sizes, int n_in,
                              void* d_out, int out_size)
{
    const float* x        = (const float*)d_in[0];
    const float* poses    = (const float*)d_in[1];
    const float* local_w  = (const float*)d_in[2];
    const float* local_b  = (const float*)d_in[3];
    const float* local_g  = (const float*)d_in[4];
    const float* local_be = (const float*)d_in[5];
    const float* local_m  = (const float*)d_in[6];
    const float* local_v  = (const float*)d_in[7];
    const float* merge_w  = (const float*)d_in[8];
    const float* merge_b  = (const float*)d_in[9];
    const float* merge_g  = (const float*)d_in[10];
    const float* merge_be = (const float*)d_in[11];
    const float* merge_m  = (const float*)d_in[12];
    const float* merge_v  = (const float*)d_in[13];
    float* out = (float*)d_out;

    boxes_masks_kernel<<<NN, HW>>>(poses);
    pool_kernel<<<dim3(CC/CT, NN), 256>>>(x);
    sgemm_splitk<0><<<dim3(CLK/64, KS, PP), 256>>>(local_w);
    epi_local<<<(NN*PC)/256, 256>>>(local_b, local_g, local_be, local_m, local_v);
    sgemm_splitk<1><<<dim3(CC/64, KS, 1), 256>>>(merge_w);
    epi_merge<<<NN, 256>>>(merge_b, merge_g, merge_be, merge_m, merge_v, out);
}

// round 4
// speedup vs baseline: 1.0196x; 1.0196x over previous
#include <cuda_runtime.h>
#include <math.h>

// ---------------------------------------------------------------------------
// Problem constants
// ---------------------------------------------------------------------------
#define NN 64
#define CC 2048
#define HH 24
#define WW 12
#define PP 5
#define CLK 256          // local out channels per pose
#define HW  (HH*WW)      // 288
#define PC  (PP*CLK)     // 1280
#define CM  (CC+PC)      // 3328
#define KSL 32           // split-K local  (kchunk 64)
#define KSM 16           // split-K merge  (kchunk 208)
#define BN_EPS 1e-5f

typedef unsigned long long ull;

// ---------------------------------------------------------------------------
// Scratch (device globals; no allocation allowed)
// ---------------------------------------------------------------------------
__device__ float    g_inv_area[NN*PP];
__device__ unsigned g_maskbits[NN*HW];        // 5-bit in-box mask per (n, hw)
__device__ float    g_avg[PP*NN*CC];          // [p][n][c] pooled averages
__device__ float    g_cat[NN*CM];             // [n][1280 loc | 2048 gfeat]
__device__ float    g_lpart[KSL*NN*PC];       // local GEMM split-K partials
__device__ float    g_mpart[KSM*NN*CC];       // merge GEMM split-K partials

// ---------------------------------------------------------------------------
// f32x2 helpers (packed dual-fp32 pipe; ptxas never auto-emits FFMA2)
// ---------------------------------------------------------------------------
__device__ __forceinline__ ull splat2(float a) {
    ull r; asm("mov.b64 %0, {%1, %1};" : "=l"(r) : "f"(a)); return r;
}
__device__ __forceinline__ void fma2(ull& d, ull a, ull b) {
    asm("fma.rn.f32x2 %0, %1, %2, %0;" : "+l"(d) : "l"(a), "l"(b));
}
__device__ __forceinline__ void unpack2(ull v, float& lo, float& hi) {
    asm("mov.b64 {%0, %1}, %2;" : "=f"(lo), "=f"(hi) : "l"(v));
}

// ---------------------------------------------------------------------------
// Kernel 1: per-(n,p) box bounds + inv_area + per-(n,hw) 5-bit masks
// ---------------------------------------------------------------------------
__global__ void boxes_masks_kernel(const float* __restrict__ poses)
{
    int n = blockIdx.x;
    __shared__ int s_box[PP][4];
    int tid = threadIdx.x;
    if (tid < PP) {
        int p = tid;
        const float* kp = poses + ((long long)n*17 + p*4)*4;  // POSE_IDS = 4*p
        float kx = kp[0], ky = kp[1], kz = kp[2];
        float bx  = fminf(fmaxf(kx - 0.25f, 0.0f), 0.75f) * kz;
        float by  = fminf(fmaxf(ky - 0.25f, 0.0f), 0.75f) * kz;
        float bwh = 0.5f * kz;
        int xs = max(0,      (int)rintf((float)WW * bx));
        int xe = min(WW - 1, (int)rintf((float)WW * (bx + bwh)));
        int ys = max(0,      (int)rintf((float)HH * by));
        int ye = min(HH - 1, (int)rintf((float)HH * (by + bwh)));
        s_box[p][0] = xs; s_box[p][1] = xe; s_box[p][2] = ys; s_box[p][3] = ye;
        int area = (ye - ys) * (xe - xs);
        g_inv_area[n*PP + p] = (area > 0) ? (1.0f / (float)area) : 1.0f;
    }
    __syncthreads();
    int idx = tid;
    if (idx < HW) {
        int h = idx / WW, w = idx % WW;
        unsigned m = 0;
        #pragma unroll
        for (int p = 0; p < PP; ++p) {
            bool in = (h >= s_box[p][2]) && (h < s_box[p][3]) &&
                      (w >= s_box[p][0]) && (w < s_box[p][1]);
            if (in) m |= (1u << p);
        }
        g_maskbits[n*HW + idx] = m;
    }
}

// ---------------------------------------------------------------------------
// Kernel 2: fused box-average pooling + global max (no smem staging of x)
// Warp cooperates across hw for 4 channels at a time; lane l owns hw = l+32k.
// Masks are channel-invariant -> preloaded per lane once.
// grid = (8 ctiles, 64 n), 256 threads
// ---------------------------------------------------------------------------
__global__ __launch_bounds__(256) void pool_kernel(const float* __restrict__ x)
{
    int n   = blockIdx.y;
    int c0  = blockIdx.x * 256;
    int tid = threadIdx.x, warp = tid >> 5, lane = tid & 31;

    __shared__ float s_avg[PP][256];
    __shared__ float s_max[256];
    __shared__ float s_inv[PP];
    if (tid < PP) s_inv[tid] = g_inv_area[n*PP + tid];

    unsigned mk[9];
    #pragma unroll
    for (int k = 0; k < 9; ++k) mk[k] = g_maskbits[n*HW + lane + 32*k];

    #pragma unroll 1
    for (int g = 0; g < 8; ++g) {
        int c = c0 + warp*32 + g*4;
        const float* b = x + ((size_t)(n*CC + c))*HW + lane;
        float v[4][9];
        #pragma unroll
        for (int q = 0; q < 4; ++q)
            #pragma unroll
            for (int k = 0; k < 9; ++k)
                v[q][k] = __ldg(b + (size_t)q*HW + 32*k);

        float s[4][PP];
        float mx[4];
        #pragma unroll
        for (int q = 0; q < 4; ++q) {
            mx[q] = -3.402823466e38f;
            #pragma unroll
            for (int p = 0; p < PP; ++p) s[q][p] = 0.f;
        }
        #pragma unroll
        for (int k = 0; k < 9; ++k) {
            unsigned m = mk[k];
            #pragma unroll
            for (int q = 0; q < 4; ++q) mx[q] = fmaxf(mx[q], v[q][k]);
            #pragma unroll
            for (int p = 0; p < PP; ++p) {
                if (m & (1u << p)) {
                    s[0][p] += v[0][k]; s[1][p] += v[1][k];
                    s[2][p] += v[2][k]; s[3][p] += v[3][k];
                }
            }
        }
        // warp-reduce 24 values
        #pragma unroll
        for (int off = 16; off > 0; off >>= 1) {
            #pragma unroll
            for (int q = 0; q < 4; ++q) {
                #pragma unroll
                for (int p = 0; p < PP; ++p)
                    s[q][p] += __shfl_xor_sync(0xffffffffu, s[q][p], off);
                mx[q] = fmaxf(mx[q], __shfl_xor_sync(0xffffffffu, mx[q], off));
            }
        }
        if (lane == 0) {
            int cc = warp*32 + g*4;
            #pragma unroll
            for (int q = 0; q < 4; ++q) {
                #pragma unroll
                for (int p = 0; p < PP; ++p) s_avg[p][cc+q] = s[q][p];
                s_max[cc+q] = mx[q];
            }
        }
    }
    __syncthreads();
    int c = c0 + tid;
    #pragma unroll
    for (int p = 0; p < PP; ++p)
        g_avg[((size_t)p*NN + n)*CC + c] = s_avg[p][tid] * s_inv[p];
    g_cat[n*CM + PC + c] = s_max[tid];
}

// ---------------------------------------------------------------------------
// Kernel 3: split-K SGEMM with packed f32x2 FMA.
// C[64, Ncols] = A[64, K] @ B[Ncols, K]^T
// Block tile 64x256, 256 threads, micro-tile 8 rows x 8 cols (cols as f32x2
// pairs, A pre-duplicated {a,a} in smem). KK = 16.
// MODE 0: local (blockIdx.x = p, 256 cols = that p's CLK, K = 2048, KS = 32)
// MODE 1: merge (blockIdx.x = coltile of 256, K = 3328, KS = 16)
// ---------------------------------------------------------------------------
#define BSPAD 264

template<int MODE>
__global__ __launch_bounds__(256) void sgemm_v2(const float* __restrict__ Bw)
{
    constexpr int LDAB   = MODE ? CM : CC;          // lda == ldb
    constexpr int NTOT   = MODE ? CC : PC;
    constexpr int KSg    = MODE ? KSM : KSL;
    constexpr int KCHUNK = (MODE ? CM : CC) / KSg;  // 208 / 64

    int ct = blockIdx.x;
    int ks = blockIdx.y;

    const float* Ab = MODE ? g_cat : (g_avg + (size_t)ct * NN * CC);
    const float* Bb = Bw + (size_t)ct * 256 * LDAB;
    float* Cp       = MODE ? g_mpart : g_lpart;
    int colbase     = ct * 256;

    __shared__ ull   As2[16][65];      // [k][row], value duplicated {a,a}
    __shared__ float Bs[16][BSPAD];    // [k][col]

    int tid = threadIdx.x;
    int tx  = tid & 31;                // col group: cols tx*4 and 128+tx*4
    int ty  = tid >> 5;                // row group: rows ty*8 .. +8

    int arow = tid >> 2;               // A load: row, 4 k-groups
    int akg  = (tid & 3) * 4;

    ull acc[8][4];                     // [row][pair]: pairs = cols {tx*4+0,1},{+2,3},{128+..}
    #pragma unroll
    for (int i = 0; i < 8; ++i)
        #pragma unroll
        for (int j = 0; j < 4; ++j) acc[i][j] = 0ull;

    int kbeg = ks * KCHUNK;
    #pragma unroll 1
    for (int k0 = kbeg; k0 < kbeg + KCHUNK; k0 += 16) {
        // ---- load A tile (64x16): 1 float4 per thread, store duplicated
        float4 a4 = *(const float4*)(Ab + (size_t)arow*LDAB + k0 + akg);
        // ---- load B tile (256x16): 4 float4 per thread (4 lanes per col)
        float4 b4[4];
        #pragma unroll
        for (int it = 0; it < 4; ++it) {
            int id  = tid + it*256;
            int col = id >> 2, kg = (id & 3) * 4;
            b4[it] = *(const float4*)(Bb + (size_t)col*LDAB + k0 + kg);
        }
        __syncthreads();
        As2[akg+0][arow] = splat2(a4.x);
        As2[akg+1][arow] = splat2(a4.y);
        As2[akg+2][arow] = splat2(a4.z);
        As2[akg+3][arow] = splat2(a4.w);
        #pragma unroll
        for (int it = 0; it < 4; ++it) {
            int id  = tid + it*256;
            int col = id >> 2, kg = (id & 3) * 4;
            Bs[kg+0][col] = b4[it].x;
            Bs[kg+1][col] = b4[it].y;
            Bs[kg+2][col] = b4[it].z;
            Bs[kg+3][col] = b4[it].w;
        }
        __syncthreads();

        #pragma unroll
        for (int kk = 0; kk < 16; ++kk) {
            ulonglong2 b0 = *(const ulonglong2*)&Bs[kk][tx*4];
            ulonglong2 b1 = *(const ulonglong2*)&Bs[kk][128 + tx*4];
            #pragma unroll
            for (int i = 0; i < 8; ++i) {
                ull a2 = As2[kk][ty*8 + i];   // broadcast LDS.64
                fma2(acc[i][0], a2, b0.x);
                fma2(acc[i][1], a2, b0.y);
                fma2(acc[i][2], a2, b1.x);
                fma2(acc[i][3], a2, b1.y);
            }
        }
    }

    // ---- store partials
    #pragma unroll
    for (int i = 0; i < 8; ++i) {
        int row = ty*8 + i;
        float4 v0, v1;
        unpack2(acc[i][0], v0.x, v0.y); unpack2(acc[i][1], v0.z, v0.w);
        unpack2(acc[i][2], v1.x, v1.y); unpack2(acc[i][3], v1.z, v1.w);
        size_t base = ((size_t)ks*NN + row) * NTOT + colbase;
        *(float4*)(Cp + base + tx*4)       = v0;
        *(float4*)(Cp + base + 128 + tx*4) = v1;
    }
}

// ---------------------------------------------------------------------------
// Kernel 4: local epilogue (vectorized) -> g_cat[:, :1280]
// grid = 80 blocks x 256 threads (20480 float4s)
// ---------------------------------------------------------------------------
__global__ __launch_bounds__(256) void epi_local(
    const float* __restrict__ lb,   const float* __restrict__ lgam,
    const float* __restrict__ lbet, const float* __restrict__ lmean,
    const float* __restrict__ lvar)
{
    int e4 = blockIdx.x * 256 + threadIdx.x;       // < 64*1280/4
    int nrow = e4 / (PC/4);
    int c4   = (e4 - nrow*(PC/4)) * 4;
    float4 a = make_float4(0.f, 0.f, 0.f, 0.f);
    #pragma unroll
    for (int ks = 0; ks < KSL; ++ks) {
        float4 t = *(const float4*)&g_lpart[((size_t)ks*NN + nrow)*PC + c4];
        a.x += t.x; a.y += t.y; a.z += t.z; a.w += t.w;
    }
    float4 vb = *(const float4*)&lb[c4];
    float4 vg = *(const float4*)&lgam[c4];
    float4 vt = *(const float4*)&lbet[c4];
    float4 vm = *(const float4*)&lmean[c4];
    float4 vv = *(const float4*)&lvar[c4];
    float4 r;
    r.x = fmaxf((a.x + vb.x - vm.x) * (vg.x * rsqrtf(vv.x + BN_EPS)) + vt.x, 0.f);
    r.y = fmaxf((a.y + vb.y - vm.y) * (vg.y * rsqrtf(vv.y + BN_EPS)) + vt.y, 0.f);
    r.z = fmaxf((a.z + vb.z - vm.z) * (vg.z * rsqrtf(vv.z + BN_EPS)) + vt.z, 0.f);
    r.w = fmaxf((a.w + vb.w - vm.w) * (vg.w * rsqrtf(vv.w + BN_EPS)) + vt.w, 0.f);
    *(float4*)&g_cat[(size_t)nrow*CM + c4] = r;
}

// ---------------------------------------------------------------------------
// Kernel 5: merge epilogue -> BN, ReLU, L2 norm, write out
// grid = 64 blocks x 256 threads; thread owns cols tid*4 and 1024+tid*4
// ---------------------------------------------------------------------------
__global__ __launch_bounds__(256) void epi_merge(
    const float* __restrict__ mb,   const float* __restrict__ mgam,
    const float* __restrict__ mbet, const float* __restrict__ mmean,
    const float* __restrict__ mvar, float* __restrict__ out)
{
    int nrow = blockIdx.x;
    int tid  = threadIdx.x;
    float y[8];
    float ss = 0.f;
    #pragma unroll
    for (int h = 0; h < 2; ++h) {
        int c4 = h*1024 + tid*4;
        float4 a = make_float4(0.f, 0.f, 0.f, 0.f);
        #pragma unroll
        for (int ks = 0; ks < KSM; ++ks) {
            float4 t = *(const float4*)&g_mpart[((size_t)ks*NN + nrow)*CC + c4];
            a.x += t.x; a.y += t.y; a.z += t.z; a.w += t.w;
        }
        float av[4] = {a.x, a.y, a.z, a.w};
        #pragma unroll
        for (int j = 0; j < 4; ++j) {
            int c = c4 + j;
            float s = av[j] + mb[c];
            float sc = mgam[c] * rsqrtf(mvar[c] + BN_EPS);
            s = (s - mmean[c]) * sc + mbet[c];
            s = fmaxf(s, 0.f);
            y[h*4 + j] = s;
            ss += s * s;
        }
    }
    __shared__ float red[256];
    red[tid] = ss;
    __syncthreads();
    #pragma unroll
    for (int o = 128; o > 0; o >>= 1) {
        if (tid < o) red[tid] += red[tid + o];
        __syncthreads();
    }
    float inv = 1.0f / fmaxf(sqrtf(red[0]), 1e-12f);
    #pragma unroll
    for (int h = 0; h < 2; ++h) {
        float4 r = make_float4(y[h*4+0]*inv, y[h*4+1]*inv, y[h*4+2]*inv, y[h*4+3]*inv);
        *(float4*)&out[(size_t)nrow*CC + h*1024 + tid*4] = r;
    }
}

// ---------------------------------------------------------------------------
// Launch
// ---------------------------------------------------------------------------
extern "C" void kernel_launch(void* const* d_in, const int* in_sizes, int n_in,
                              void* d_out, int out_size)
{
    const float* x        = (const float*)d_in[0];
    const float* poses    = (const float*)d_in[1];
    const float* local_w  = (const float*)d_in[2];
    const float* local_b  = (const float*)d_in[3];
    const float* local_g  = (const float*)d_in[4];
    const float* local_be = (const float*)d_in[5];
    const float* local_m  = (const float*)d_in[6];
    const float* local_v  = (const float*)d_in[7];
    const float* merge_w  = (const float*)d_in[8];
    const float* merge_b  = (const float*)d_in[9];
    const float* merge_g  = (const float*)d_in[10];
    const float* merge_be = (const float*)d_in[11];
    const float* merge_m  = (const float*)d_in[12];
    const float* merge_v  = (const float*)d_in[13];
    float* out = (float*)d_out;

    boxes_masks_kernel<<<NN, HW>>>(poses);
    pool_kernel<<<dim3(CC/256, NN), 256>>>(x);
    sgemm_v2<0><<<dim3(PP, KSL), 256>>>(local_w);
    epi_local<<<(NN*PC/4)/256, 256>>>(local_b, local_g, local_be, local_m, local_v);
    sgemm_v2<1><<<dim3(CC/256, KSM), 256>>>(merge_w);
    epi_merge<<<NN, 256>>>(merge_b, merge_g, merge_be, merge_m, merge_v, out);
}

// round 9
// speedup vs baseline: 1.3263x; 1.3008x over previous
#include <cuda_runtime.h>
#include <cuda_bf16.h>
#include <math.h>
#include <cstdint>

// ---------------------------------------------------------------------------
// Problem constants
// ---------------------------------------------------------------------------
#define NN 64
#define CC 2048
#define HH 24
#define WW 12
#define PP 5
#define CLK 256
#define HW  (HH*WW)      // 288
#define PC  (PP*CLK)     // 1280
#define CM  (CC+PC)      // 3328
#define KSL 16           // split-K local  (kchunk 128, 2 stages)
#define KSM 13           // split-K merge  (kchunk 256, 4 stages)
#define BN_EPS 1e-5f

// ---------------------------------------------------------------------------
// Scratch
// ---------------------------------------------------------------------------
__device__ float    g_inv_area[NN*PP];
__device__ unsigned g_maskbits[NN*HW];
__device__ float    g_avg[PP*NN*CC];
__device__ float    g_cat[NN*CM];
__device__ float    g_lpart[KSL*NN*PC];
__device__ float    g_mpart[KSM*NN*CC];

// ---------------------------------------------------------------------------
// PTX helpers (baseline sm_80-class instructions only; NO tcgen05)
// ---------------------------------------------------------------------------
__device__ __forceinline__ uint32_t smem_u32(const void* p) {
    uint32_t a;
    asm("{ .reg .u64 t; cvta.to.shared.u64 t, %1; cvt.u32.u64 %0, t; }" : "=r"(a) : "l"(p));
    return a;
}
__device__ __forceinline__ void ldsm4(uint32_t* r, uint32_t addr) {
    asm volatile("ldmatrix.sync.aligned.m8n8.x4.shared.b16 {%0,%1,%2,%3}, [%4];"
        : "=r"(r[0]), "=r"(r[1]), "=r"(r[2]), "=r"(r[3]) : "r"(addr));
}
__device__ __forceinline__ void mma_bf16(float* d, const uint32_t* a,
                                         uint32_t b0, uint32_t b1) {
    asm volatile(
        "mma.sync.aligned.m16n8k16.row.col.f32.bf16.bf16.f32 "
        "{%0,%1,%2,%3}, {%4,%5,%6,%7}, {%8,%9}, {%0,%1,%2,%3};"
        : "+f"(d[0]), "+f"(d[1]), "+f"(d[2]), "+f"(d[3])
        : "r"(a[0]), "r"(a[1]), "r"(a[2]), "r"(a[3]), "r"(b0), "r"(b1));
}

// fp32 -> bf16 hi/lo split of 8 contiguous values; 16B store per plane at sw.
__device__ __forceinline__ void cvt_store8(const float* __restrict__ src,
                                           char* hip, char* lop, uint32_t sw)
{
    float4 f0 = *(const float4*)src;
    float4 f1 = *(const float4*)(src + 4);
    float f[8] = {f0.x, f0.y, f0.z, f0.w, f1.x, f1.y, f1.z, f1.w};
    unsigned short h[8], l[8];
    #pragma unroll
    for (int i = 0; i < 8; ++i) {
        __nv_bfloat16 bh = __float2bfloat16_rn(f[i]);
        float r = f[i] - __bfloat162float(bh);
        __nv_bfloat16 bl = __float2bfloat16_rn(r);
        h[i] = __bfloat16_as_ushort(bh);
        l[i] = __bfloat16_as_ushort(bl);
    }
    uint4 vh, vl;
    vh.x = (uint32_t)h[0] | ((uint32_t)h[1] << 16);
    vh.y = (uint32_t)h[2] | ((uint32_t)h[3] << 16);
    vh.z = (uint32_t)h[4] | ((uint32_t)h[5] << 16);
    vh.w = (uint32_t)h[6] | ((uint32_t)h[7] << 16);
    vl.x = (uint32_t)l[0] | ((uint32_t)l[1] << 16);
    vl.y = (uint32_t)l[2] | ((uint32_t)l[3] << 16);
    vl.z = (uint32_t)l[4] | ((uint32_t)l[5] << 16);
    vl.w = (uint32_t)l[6] | ((uint32_t)l[7] << 16);
    *(uint4*)(hip + sw) = vh;
    *(uint4*)(lop + sw) = vl;
}

// ---------------------------------------------------------------------------
// Kernel 1: boxes + masks
// ---------------------------------------------------------------------------
__global__ void boxes_masks_kernel(const float* __restrict__ poses)
{
    int n = blockIdx.x;
    __shared__ int s_box[PP][4];
    int tid = threadIdx.x;
    if (tid < PP) {
        int p = tid;
        const float* kp = poses + ((long long)n*17 + p*4)*4;
        float kx = kp[0], ky = kp[1], kz = kp[2];
        float bx  = fminf(fmaxf(kx - 0.25f, 0.0f), 0.75f) * kz;
        float by  = fminf(fmaxf(ky - 0.25f, 0.0f), 0.75f) * kz;
        float bwh = 0.5f * kz;
        int xs = max(0,      (int)rintf((float)WW * bx));
        int xe = min(WW - 1, (int)rintf((float)WW * (bx + bwh)));
        int ys = max(0,      (int)rintf((float)HH * by));
        int ye = min(HH - 1, (int)rintf((float)HH * (by + bwh)));
        s_box[p][0] = xs; s_box[p][1] = xe; s_box[p][2] = ys; s_box[p][3] = ye;
        int area = (ye - ys) * (xe - xs);
        g_inv_area[n*PP + p] = (area > 0) ? (1.0f / (float)area) : 1.0f;
    }
    __syncthreads();
    int idx = tid;
    if (idx < HW) {
        int h = idx / WW, w = idx % WW;
        unsigned m = 0;
        #pragma unroll
        for (int p = 0; p < PP; ++p) {
            bool in = (h >= s_box[p][2]) && (h < s_box[p][3]) &&
                      (w >= s_box[p][0]) && (w < s_box[p][1]);
            if (in) m |= (1u << p);
        }
        g_maskbits[n*HW + idx] = m;
    }
}

// ---------------------------------------------------------------------------
// Kernel 2: pooling + global max (unchanged passing version)
// ---------------------------------------------------------------------------
__global__ __launch_bounds__(256) void pool_kernel(const float* __restrict__ x)
{
    int n   = blockIdx.y;
    int c0  = blockIdx.x * 256;
    int tid = threadIdx.x, warp = tid >> 5, lane = tid & 31;

    __shared__ float s_avg[PP][256];
    __shared__ float s_max[256];
    __shared__ float s_inv[PP];
    if (tid < PP) s_inv[tid] = g_inv_area[n*PP + tid];

    unsigned mk[9];
    #pragma unroll
    for (int k = 0; k < 9; ++k) mk[k] = g_maskbits[n*HW + lane + 32*k];

    #pragma unroll 1
    for (int g = 0; g < 8; ++g) {
        int c = c0 + warp*32 + g*4;
        const float* b = x + ((size_t)(n*CC + c))*HW + lane;
        float v[4][9];
        #pragma unroll
        for (int q = 0; q < 4; ++q)
            #pragma unroll
            for (int k = 0; k < 9; ++k)
                v[q][k] = __ldg(b + (size_t)q*HW + 32*k);

        float s[4][PP];
        float mx[4];
        #pragma unroll
        for (int q = 0; q < 4; ++q) {
            mx[q] = -3.402823466e38f;
            #pragma unroll
            for (int p = 0; p < PP; ++p) s[q][p] = 0.f;
        }
        #pragma unroll
        for (int k = 0; k < 9; ++k) {
            unsigned m = mk[k];
            #pragma unroll
            for (int q = 0; q < 4; ++q) mx[q] = fmaxf(mx[q], v[q][k]);
            #pragma unroll
            for (int p = 0; p < PP; ++p) {
                if (m & (1u << p)) {
                    s[0][p] += v[0][k]; s[1][p] += v[1][k];
                    s[2][p] += v[2][k]; s[3][p] += v[3][k];
                }
            }
        }
        #pragma unroll
        for (int off = 16; off > 0; off >>= 1) {
            #pragma unroll
            for (int q = 0; q < 4; ++q) {
                #pragma unroll
                for (int p = 0; p < PP; ++p)
                    s[q][p] += __shfl_xor_sync(0xffffffffu, s[q][p], off);
                mx[q] = fmaxf(mx[q], __shfl_xor_sync(0xffffffffu, mx[q], off));
            }
        }
        if (lane == 0) {
            int cc = warp*32 + g*4;
            #pragma unroll
            for (int q = 0; q < 4; ++q) {
                #pragma unroll
                for (int p = 0; p < PP; ++p) s_avg[p][cc+q] = s[q][p];
                s_max[cc+q] = mx[q];
            }
        }
    }
    __syncthreads();
    int c = c0 + tid;
    #pragma unroll
    for (int p = 0; p < PP; ++p)
        g_avg[((size_t)p*NN + n)*CC + c] = s_avg[p][tid] * s_inv[p];
    g_cat[n*CM + PC + c] = s_max[tid];
}

// ---------------------------------------------------------------------------
// Kernel 3: warp-MMA bf16x3 split-K GEMM.
// C[64, *] = A[64,K] @ B[*,K]^T (fp32 in, fp32 partials out)
// Block: 64x128 tile, 8 warps (warp = 16 rows x 64 cols = 8 m16n8 acc tiles).
// Per stage (64 k): fp32 -> bf16 hi/lo planes in swizzled smem; non-trans
// ldmatrix for BOTH operands (B stored [n][k] makes its fragment A-like).
// 3 accumulating passes: hi*hi + hi*lo + lo*hi.
// smem planes: A_hi[0,8K) A_lo[8K,16K) B_hi[16K,32K) B_lo[32K,48K)
// ---------------------------------------------------------------------------
#define SMEMG (49152 + 1024)

template<int MODE>
__global__ __launch_bounds__(256) void wgemm(const float* __restrict__ Bw)
{
    constexpr int LDAB = MODE ? CM : CC;
    constexpr int NTOT = MODE ? CC : PC;
    constexpr int KSg  = MODE ? KSM : KSL;
    constexpr int KCH  = (MODE ? CM : CC) / KSg;   // 256 / 128
    constexpr int NST  = KCH / 64;                 // 4 / 2

    extern __shared__ char smraw[];
    uint32_t rawu  = smem_u32(smraw);
    uint32_t sbase = (rawu + 127) & ~127u;
    char* sm = smraw + (sbase - rawu);

    int tid = threadIdx.x, wid = tid >> 5, lane = tid & 31;
    int ct = blockIdx.x, ks = blockIdx.y;

    const float* Ab = MODE ? g_cat : (g_avg + (size_t)(ct >> 1) * NN * CC);
    const float* Bb = Bw + (size_t)ct * 128 * LDAB;
    float* Cp = MODE ? g_mpart : g_lpart;
    int colbase = ct * 128;

    // warp tile: rows r0..r0+15, cols c0w..c0w+63
    int r0  = (wid & 3) * 16;
    int c0w = (wid >> 2) * 64;

    // ldmatrix lane addressing (non-trans, canonical fragment order)
    int aRow = r0 + (lane & 15);                       // lanes 0-15 rows, 16-31 repeat
    uint32_t aOffBase = (uint32_t)aRow * 128;
    uint32_t aRot     = (uint32_t)(aRow & 7) << 4;
    uint32_t aK       = (uint32_t)(lane >> 4) * 16;    // k-part byte offset
    int bnrel         = (lane & 7) + ((lane >> 4) << 3);
    uint32_t bK       = (uint32_t)((lane >> 3) & 1) * 16;

    float acc[8][4];
    #pragma unroll
    for (int t = 0; t < 8; ++t) { acc[t][0]=acc[t][1]=acc[t][2]=acc[t][3]=0.f; }

    int kbeg = ks * KCH;
    #pragma unroll 1
    for (int st = 0; st < NST; ++st) {
        int k0 = kbeg + st * 64;
        // ---- stage A (64x64): 512 8-float groups, 2 per thread
        #pragma unroll
        for (int i = 0; i < 2; ++i) {
            int g = tid + i * 256;
            int r = g >> 3, c = (g & 7) * 8;
            uint32_t off = (uint32_t)r*128 + (((uint32_t)c*2) ^ (((uint32_t)(r&7))<<4));
            cvt_store8(Ab + (size_t)r*LDAB + k0 + c, sm, sm + 8192, off);
        }
        // ---- stage B (128x64): 1024 groups, 4 per thread
        #pragma unroll
        for (int i = 0; i < 4; ++i) {
            int g = tid + i * 256;
            int r = g >> 3, c = (g & 7) * 8;
            uint32_t off = (uint32_t)r*128 + (((uint32_t)c*2) ^ (((uint32_t)(r&7))<<4));
            cvt_store8(Bb + (size_t)r*LDAB + k0 + c, sm + 16384, sm + 32768, off);
        }
        __syncthreads();

        #pragma unroll
        for (int kk = 0; kk < 4; ++kk) {
            uint32_t k2 = (uint32_t)kk * 32;           // k16 step in bytes
            uint32_t aoff = aOffBase + ((k2 + aK) ^ aRot);
            uint32_t Ahi[4], Alo[4];
            ldsm4(Ahi, sbase + aoff);
            ldsm4(Alo, sbase + 8192 + aoff);
            #pragma unroll
            for (int gq = 0; gq < 4; ++gq) {
                int brow = c0w + gq*16 + bnrel;
                uint32_t boff = (uint32_t)brow*128 +
                                ((k2 + bK) ^ (((uint32_t)(brow & 7)) << 4));
                uint32_t Bh[4], Bl[4];
                ldsm4(Bh, sbase + 16384 + boff);
                ldsm4(Bl, sbase + 32768 + boff);
                #pragma unroll
                for (int hf = 0; hf < 2; ++hf) {
                    float* d = acc[gq*2 + hf];
                    mma_bf16(d, Ahi, Bh[hf*2], Bh[hf*2+1]);
                    mma_bf16(d, Ahi, Bl[hf*2], Bl[hf*2+1]);
                    mma_bf16(d, Alo, Bh[hf*2], Bh[hf*2+1]);
                }
            }
        }
        __syncthreads();
    }

    // ---- store partials (PTX-defined accumulator layout)
    int grow = lane >> 2, gcol = (lane & 3) * 2;
    #pragma unroll
    for (int t = 0; t < 8; ++t) {
        int col = colbase + c0w + t*8 + gcol;
        size_t idx0 = ((size_t)ks*NN + r0 + grow) * NTOT + col;
        size_t idx1 = idx0 + (size_t)8 * NTOT;
        *(float2*)&Cp[idx0] = make_float2(acc[t][0], acc[t][1]);
        *(float2*)&Cp[idx1] = make_float2(acc[t][2], acc[t][3]);
    }
}

// ---------------------------------------------------------------------------
// Kernel 4: local epilogue
// ---------------------------------------------------------------------------
__global__ __launch_bounds__(256) void epi_local(
    const float* __restrict__ lb,   const float* __restrict__ lgam,
    const float* __restrict__ lbet, const float* __restrict__ lmean,
    const float* __restrict__ lvar)
{
    int e4 = blockIdx.x * 256 + threadIdx.x;
    int nrow = e4 / (PC/4);
    int c4   = (e4 - nrow*(PC/4)) * 4;
    float4 a = make_float4(0.f, 0.f, 0.f, 0.f);
    #pragma unroll
    for (int ks = 0; ks < KSL; ++ks) {
        float4 t = *(const float4*)&g_lpart[((size_t)ks*NN + nrow)*PC + c4];
        a.x += t.x; a.y += t.y; a.z += t.z; a.w += t.w;
    }
    float4 vb = *(const float4*)&lb[c4];
    float4 vg = *(const float4*)&lgam[c4];
    float4 vt = *(const float4*)&lbet[c4];
    float4 vm = *(const float4*)&lmean[c4];
    float4 vv = *(const float4*)&lvar[c4];
    float4 r;
    r.x = fmaxf((a.x + vb.x - vm.x) * (vg.x * rsqrtf(vv.x + BN_EPS)) + vt.x, 0.f);
    r.y = fmaxf((a.y + vb.y - vm.y) * (vg.y * rsqrtf(vv.y + BN_EPS)) + vt.y, 0.f);
    r.z = fmaxf((a.z + vb.z - vm.z) * (vg.z * rsqrtf(vv.z + BN_EPS)) + vt.z, 0.f);
    r.w = fmaxf((a.w + vb.w - vm.w) * (vg.w * rsqrtf(vv.w + BN_EPS)) + vt.w, 0.f);
    *(float4*)&g_cat[(size_t)nrow*CM + c4] = r;
}

// ---------------------------------------------------------------------------
// Kernel 5: merge epilogue
// ---------------------------------------------------------------------------
__global__ __launch_bounds__(256) void epi_merge(
    const float* __restrict__ mb,   const float* __restrict__ mgam,
    const float* __restrict__ mbet, const float* __restrict__ mmean,
    const float* __restrict__ mvar, float* __restrict__ out)
{
    int nrow = blockIdx.x;
    int tid  = threadIdx.x;
    float y[8];
    float ss = 0.f;
    #pragma unroll
    for (int h = 0; h < 2; ++h) {
        int c4 = h*1024 + tid*4;
        float4 a = make_float4(0.f, 0.f, 0.f, 0.f);
        #pragma unroll
        for (int ks = 0; ks < KSM; ++ks) {
            float4 t = *(const float4*)&g_mpart[((size_t)ks*NN + nrow)*CC + c4];
            a.x += t.x; a.y += t.y; a.z += t.z; a.w += t.w;
        }
        float av[4] = {a.x, a.y, a.z, a.w};
        #pragma unroll
        for (int j = 0; j < 4; ++j) {
            int c = c4 + j;
            float s = av[j] + mb[c];
            float sc = mgam[c] * rsqrtf(mvar[c] + BN_EPS);
            s = (s - mmean[c]) * sc + mbet[c];
            s = fmaxf(s, 0.f);
            y[h*4 + j] = s;
            ss += s * s;
        }
    }
    __shared__ float red[256];
    red[tid] = ss;
    __syncthreads();
    #pragma unroll
    for (int o = 128; o > 0; o >>= 1) {
        if (tid < o) red[tid] += red[tid + o];
        __syncthreads();
    }
    float inv = 1.0f / fmaxf(sqrtf(red[0]), 1e-12f);
    #pragma unroll
    for (int h = 0; h < 2; ++h) {
        float4 r = make_float4(y[h*4+0]*inv, y[h*4+1]*inv, y[h*4+2]*inv, y[h*4+3]*inv);
        *(float4*)&out[(size_t)nrow*CC + h*1024 + tid*4] = r;
    }
}

// ---------------------------------------------------------------------------
// Launch
// ---------------------------------------------------------------------------
extern "C" void kernel_launch(void* const* d_in, const int* in_sizes, int n_in,
                              void* d_out, int out_size)
{
    const float* x        = (const float*)d_in[0];
    const float* poses    = (const float*)d_in[1];
    const float* local_w  = (const float*)d_in[2];
    const float* local_b  = (const float*)d_in[3];
    const float* local_g  = (const float*)d_in[4];
    const float* local_be = (const float*)d_in[5];
    const float* local_m  = (const float*)d_in[6];
    const float* local_v  = (const float*)d_in[7];
    const float* merge_w  = (const float*)d_in[8];
    const float* merge_b  = (const float*)d_in[9];
    const float* merge_g  = (const float*)d_in[10];
    const float* merge_be = (const float*)d_in[11];
    const float* merge_m  = (const float*)d_in[12];
    const float* merge_v  = (const float*)d_in[13];
    float* out = (float*)d_out;

    cudaFuncSetAttribute(wgemm<0>, cudaFuncAttributeMaxDynamicSharedMemorySize, SMEMG);
    cudaFuncSetAttribute(wgemm<1>, cudaFuncAttributeMaxDynamicSharedMemorySize, SMEMG);

    boxes_masks_kernel<<<NN, HW>>>(poses);
    pool_kernel<<<dim3(CC/256, NN), 256>>>(x);
    wgemm<0><<<dim3(PC/128, KSL), 256, SMEMG>>>(local_w);
    epi_local<<<(NN*PC/4)/256, 256>>>(local_b, local_g, local_be, local_m, local_v);
    wgemm<1><<<dim3(CC/128, KSM), 256, SMEMG>>>(merge_w);
    epi_merge<<<NN, 256>>>(merge_b, merge_g, merge_be, merge_m, merge_v, out);
}

// round 10
// speedup vs baseline: 1.4163x; 1.0678x over previous
#include <cuda_runtime.h>
#include <cuda_bf16.h>
#include <math.h>
#include <cstdint>

// ---------------------------------------------------------------------------
// Problem constants
// ---------------------------------------------------------------------------
#define NN 64
#define CC 2048
#define HH 24
#define WW 12
#define PP 5
#define CLK 256
#define HW  (HH*WW)      // 288
#define PC  (PP*CLK)     // 1280
#define CM  (CC+PC)      // 3328
#define KSL 16           // split-K local  (kchunk 128, 2 stages)
#define KSM 13           // split-K merge  (kchunk 256, 4 stages)
#define BN_EPS 1e-5f

// ---------------------------------------------------------------------------
// Scratch
// ---------------------------------------------------------------------------
__device__ float g_avg[PP*NN*CC];
__device__ float g_cat[NN*CM];
__device__ float g_lpart[KSL*NN*PC];
__device__ float g_mpart[KSM*NN*CC];
__device__ float g_ss[NN*4];

// ---------------------------------------------------------------------------
// PTX helpers (baseline sm_80-class instructions only; NO tcgen05)
// ---------------------------------------------------------------------------
__device__ __forceinline__ uint32_t smem_u32(const void* p) {
    uint32_t a;
    asm("{ .reg .u64 t; cvta.to.shared.u64 t, %1; cvt.u32.u64 %0, t; }" : "=r"(a) : "l"(p));
    return a;
}
__device__ __forceinline__ void ldsm4(uint32_t* r, uint32_t addr) {
    asm volatile("ldmatrix.sync.aligned.m8n8.x4.shared.b16 {%0,%1,%2,%3}, [%4];"
        : "=r"(r[0]), "=r"(r[1]), "=r"(r[2]), "=r"(r[3]) : "r"(addr));
}
__device__ __forceinline__ void mma_bf16(float* d, const uint32_t* a,
                                         uint32_t b0, uint32_t b1) {
    asm volatile(
        "mma.sync.aligned.m16n8k16.row.col.f32.bf16.bf16.f32 "
        "{%0,%1,%2,%3}, {%4,%5,%6,%7}, {%8,%9}, {%0,%1,%2,%3};"
        : "+f"(d[0]), "+f"(d[1]), "+f"(d[2]), "+f"(d[3])
        : "r"(a[0]), "r"(a[1]), "r"(a[2]), "r"(a[3]), "r"(b0), "r"(b1));
}

// fp32 -> bf16 hi/lo split of 8 contiguous values; 16B store per plane at sw.
__device__ __forceinline__ void cvt_store8(const float* __restrict__ src,
                                           char* hip, char* lop, uint32_t sw)
{
    float4 f0 = *(const float4*)src;
    float4 f1 = *(const float4*)(src + 4);
    float f[8] = {f0.x, f0.y, f0.z, f0.w, f1.x, f1.y, f1.z, f1.w};
    unsigned short h[8], l[8];
    #pragma unroll
    for (int i = 0; i < 8; ++i) {
        __nv_bfloat16 bh = __float2bfloat16_rn(f[i]);
        float r = f[i] - __bfloat162float(bh);
        __nv_bfloat16 bl = __float2bfloat16_rn(r);
        h[i] = __bfloat16_as_ushort(bh);
        l[i] = __bfloat16_as_ushort(bl);
    }
    uint4 vh, vl;
    vh.x = (uint32_t)h[0] | ((uint32_t)h[1] << 16);
    vh.y = (uint32_t)h[2] | ((uint32_t)h[3] << 16);
    vh.z = (uint32_t)h[4] | ((uint32_t)h[5] << 16);
    vh.w = (uint32_t)h[6] | ((uint32_t)h[7] << 16);
    vl.x = (uint32_t)l[0] | ((uint32_t)l[1] << 16);
    vl.y = (uint32_t)l[2] | ((uint32_t)l[3] << 16);
    vl.z = (uint32_t)l[4] | ((uint32_t)l[5] << 16);
    vl.w = (uint32_t)l[6] | ((uint32_t)l[7] << 16);
    *(uint4*)(hip + sw) = vh;
    *(uint4*)(lop + sw) = vl;
}

// ---------------------------------------------------------------------------
// Kernel 1: fused boxes + pooling + global max.
// Boxes recomputed per block (trivial). smem-transpose reduction instead of
// shfl butterfly (conflict-free stride-25 layout).
// grid = (8 ctiles, 64 n), 256 threads
// ---------------------------------------------------------------------------
__global__ __launch_bounds__(256) void pool_kernel(const float* __restrict__ x,
                                                   const float* __restrict__ poses)
{
    int n   = blockIdx.y;
    int c0  = blockIdx.x * 256;
    int tid = threadIdx.x, warp = tid >> 5, lane = tid & 31;

    __shared__ int   s_box[PP][4];
    __shared__ float s_inv[PP];
    __shared__ float s_avg[PP][256];
    __shared__ float s_max[256];
    __shared__ float s_red[8][32][25];

    if (tid < PP) {
        int p = tid;
        const float* kp = poses + ((long long)n*17 + p*4)*4;
        float kx = kp[0], ky = kp[1], kz = kp[2];
        float bx  = fminf(fmaxf(kx - 0.25f, 0.0f), 0.75f) * kz;
        float by  = fminf(fmaxf(ky - 0.25f, 0.0f), 0.75f) * kz;
        float bwh = 0.5f * kz;
        int xs = max(0,      (int)rintf((float)WW * bx));
        int xe = min(WW - 1, (int)rintf((float)WW * (bx + bwh)));
        int ys = max(0,      (int)rintf((float)HH * by));
        int ye = min(HH - 1, (int)rintf((float)HH * (by + bwh)));
        s_box[p][0] = xs; s_box[p][1] = xe; s_box[p][2] = ys; s_box[p][3] = ye;
        int area = (ye - ys) * (xe - xs);
        s_inv[p] = (area > 0) ? (1.0f / (float)area) : 1.0f;
    }
    __syncthreads();

    // per-lane 5-bit masks for hw = lane + 32k
    unsigned mk[9];
    #pragma unroll
    for (int k = 0; k < 9; ++k) {
        int hw = lane + 32*k;
        int h = hw / WW, w = hw % WW;
        unsigned m = 0;
        #pragma unroll
        for (int p = 0; p < PP; ++p) {
            bool in = (h >= s_box[p][2]) && (h < s_box[p][3]) &&
                      (w >= s_box[p][0]) && (w < s_box[p][1]);
            if (in) m |= (1u << p);
        }
        mk[k] = m;
    }

    #pragma unroll 1
    for (int g = 0; g < 8; ++g) {
        int c = c0 + warp*32 + g*4;
        const float* b = x + ((size_t)(n*CC + c))*HW + lane;
        float v[4][9];
        #pragma unroll
        for (int q = 0; q < 4; ++q)
            #pragma unroll
            for (int k = 0; k < 9; ++k)
                v[q][k] = __ldg(b + (size_t)q*HW + 32*k);

        float s[4][PP];
        float mx[4];
        #pragma unroll
        for (int q = 0; q < 4; ++q) {
            mx[q] = -3.402823466e38f;
            #pragma unroll
            for (int p = 0; p < PP; ++p) s[q][p] = 0.f;
        }
        #pragma unroll
        for (int k = 0; k < 9; ++k) {
            unsigned m = mk[k];
            #pragma unroll
            for (int q = 0; q < 4; ++q) mx[q] = fmaxf(mx[q], v[q][k]);
            #pragma unroll
            for (int p = 0; p < PP; ++p) {
                if (m & (1u << p)) {
                    s[0][p] += v[0][k]; s[1][p] += v[1][k];
                    s[2][p] += v[2][k]; s[3][p] += v[3][k];
                }
            }
        }
        // smem transpose reduce: lane writes its 24 values, lanes 0-23 sum rows
        #pragma unroll
        for (int q = 0; q < 4; ++q) {
            #pragma unroll
            for (int p = 0; p < PP; ++p) s_red[warp][lane][q*6 + p] = s[q][p];
            s_red[warp][lane][q*6 + 5] = mx[q];
        }
        __syncwarp();
        if (lane < 24) {
            float a0 = 0.f, a1 = 0.f, a2 = 0.f, a3 = 0.f;
            #pragma unroll
            for (int l = 0; l < 32; l += 4) {
                a0 += s_red[warp][l+0][lane];
                a1 += s_red[warp][l+1][lane];
                a2 += s_red[warp][l+2][lane];
                a3 += s_red[warp][l+3][lane];
            }
            int q = lane / 6, r = lane - q*6;
            int ch = warp*32 + g*4 + q;
            if (r < 5) s_avg[r][ch] = (a0 + a1) + (a2 + a3);
            else {
                float m0 = fmaxf(fmaxf(s_red[warp][0][lane], 0.f), 0.f); // placeholder avoided below
                // max must be max-reduced, not summed:
                m0 = s_red[warp][0][lane];
                #pragma unroll
                for (int l = 1; l < 32; ++l) m0 = fmaxf(m0, s_red[warp][l][lane]);
                s_max[ch] = m0;
            }
        }
        __syncwarp();
    }
    __syncthreads();
    int c = c0 + tid;
    #pragma unroll
    for (int p = 0; p < PP; ++p)
        g_avg[((size_t)p*NN + n)*CC + c] = s_avg[p][tid] * s_inv[p];
    g_cat[n*CM + PC + c] = s_max[tid];
}

// ---------------------------------------------------------------------------
// Kernel 2: warp-MMA bf16x3 split-K GEMM (unchanged from passing R9 version)
// ---------------------------------------------------------------------------
#define SMEMG (49152 + 1024)

template<int MODE>
__global__ __launch_bounds__(256) void wgemm(const float* __restrict__ Bw)
{
    constexpr int LDAB = MODE ? CM : CC;
    constexpr int NTOT = MODE ? CC : PC;
    constexpr int KSg  = MODE ? KSM : KSL;
    constexpr int KCH  = (MODE ? CM : CC) / KSg;   // 256 / 128
    constexpr int NST  = KCH / 64;                 // 4 / 2

    extern __shared__ char smraw[];
    uint32_t rawu  = smem_u32(smraw);
    uint32_t sbase = (rawu + 127) & ~127u;
    char* sm = smraw + (sbase - rawu);

    int tid = threadIdx.x, wid = tid >> 5, lane = tid & 31;
    int ct = blockIdx.x, ks = blockIdx.y;

    const float* Ab = MODE ? g_cat : (g_avg + (size_t)(ct >> 1) * NN * CC);
    const float* Bb = Bw + (size_t)ct * 128 * LDAB;
    float* Cp = MODE ? g_mpart : g_lpart;
    int colbase = ct * 128;

    int r0  = (wid & 3) * 16;
    int c0w = (wid >> 2) * 64;

    int aRow = r0 + (lane & 15);
    uint32_t aOffBase = (uint32_t)aRow * 128;
    uint32_t aRot     = (uint32_t)(aRow & 7) << 4;
    uint32_t aK       = (uint32_t)(lane >> 4) * 16;
    int bnrel         = (lane & 7) + ((lane >> 4) << 3);
    uint32_t bK       = (uint32_t)((lane >> 3) & 1) * 16;

    float acc[8][4];
    #pragma unroll
    for (int t = 0; t < 8; ++t) { acc[t][0]=acc[t][1]=acc[t][2]=acc[t][3]=0.f; }

    int kbeg = ks * KCH;
    #pragma unroll 1
    for (int st = 0; st < NST; ++st) {
        int k0 = kbeg + st * 64;
        #pragma unroll
        for (int i = 0; i < 2; ++i) {
            int g = tid + i * 256;
            int r = g >> 3, c = (g & 7) * 8;
            uint32_t off = (uint32_t)r*128 + (((uint32_t)c*2) ^ (((uint32_t)(r&7))<<4));
            cvt_store8(Ab + (size_t)r*LDAB + k0 + c, sm, sm + 8192, off);
        }
        #pragma unroll
        for (int i = 0; i < 4; ++i) {
            int g = tid + i * 256;
            int r = g >> 3, c = (g & 7) * 8;
            uint32_t off = (uint32_t)r*128 + (((uint32_t)c*2) ^ (((uint32_t)(r&7))<<4));
            cvt_store8(Bb + (size_t)r*LDAB + k0 + c, sm + 16384, sm + 32768, off);
        }
        __syncthreads();

        #pragma unroll
        for (int kk = 0; kk < 4; ++kk) {
            uint32_t k2 = (uint32_t)kk * 32;
            uint32_t aoff = aOffBase + ((k2 + aK) ^ aRot);
            uint32_t Ahi[4], Alo[4];
            ldsm4(Ahi, sbase + aoff);
            ldsm4(Alo, sbase + 8192 + aoff);
            #pragma unroll
            for (int gq = 0; gq < 4; ++gq) {
                int brow = c0w + gq*16 + bnrel;
                uint32_t boff = (uint32_t)brow*128 +
                                ((k2 + bK) ^ (((uint32_t)(brow & 7)) << 4));
                uint32_t Bh[4], Bl[4];
                ldsm4(Bh, sbase + 16384 + boff);
                ldsm4(Bl, sbase + 32768 + boff);
                #pragma unroll
                for (int hf = 0; hf < 2; ++hf) {
                    float* d = acc[gq*2 + hf];
                    mma_bf16(d, Ahi, Bh[hf*2], Bh[hf*2+1]);
                    mma_bf16(d, Ahi, Bl[hf*2], Bl[hf*2+1]);
                    mma_bf16(d, Alo, Bh[hf*2], Bh[hf*2+1]);
                }
            }
        }
        __syncthreads();
    }

    int grow = lane >> 2, gcol = (lane & 3) * 2;
    #pragma unroll
    for (int t = 0; t < 8; ++t) {
        int col = colbase + c0w + t*8 + gcol;
        size_t idx0 = ((size_t)ks*NN + r0 + grow) * NTOT + col;
        size_t idx1 = idx0 + (size_t)8 * NTOT;
        *(float2*)&Cp[idx0] = make_float2(acc[t][0], acc[t][1]);
        *(float2*)&Cp[idx1] = make_float2(acc[t][2], acc[t][3]);
    }
}

// ---------------------------------------------------------------------------
// Kernel 3: local epilogue, 4-way ks-split + smem combine.
// grid = 320 blocks x 256 threads; 64 float4-outputs per block.
// ---------------------------------------------------------------------------
__global__ __launch_bounds__(256) void epi_local(
    const float* __restrict__ lb,   const float* __restrict__ lgam,
    const float* __restrict__ lbet, const float* __restrict__ lmean,
    const float* __restrict__ lvar)
{
    int tid  = threadIdx.x;
    int out  = tid & 63;
    int part = tid >> 6;                     // 0..3 -> ks 4*part..+3
    int e4   = blockIdx.x * 64 + out;        // < 20480
    int nrow = e4 / (PC/4);
    int c4   = (e4 - nrow*(PC/4)) * 4;

    float4 a = make_float4(0.f, 0.f, 0.f, 0.f);
    #pragma unroll
    for (int i = 0; i < 4; ++i) {
        int ks = part*4 + i;
        float4 t = *(const float4*)&g_lpart[((size_t)ks*NN + nrow)*PC + c4];
        a.x += t.x; a.y += t.y; a.z += t.z; a.w += t.w;
    }
    __shared__ float4 sred[4][64];
    sred[part][out] = a;
    __syncthreads();
    if (tid < 64) {
        float4 a0 = sred[0][tid], a1 = sred[1][tid], a2 = sred[2][tid], a3 = sred[3][tid];
        a.x = (a0.x + a1.x) + (a2.x + a3.x);
        a.y = (a0.y + a1.y) + (a2.y + a3.y);
        a.z = (a0.z + a1.z) + (a2.z + a3.z);
        a.w = (a0.w + a1.w) + (a2.w + a3.w);
        int e = blockIdx.x * 64 + tid;
        int nr = e / (PC/4);
        int cc = (e - nr*(PC/4)) * 4;
        float4 vb = *(const float4*)&lb[cc];
        float4 vg = *(const float4*)&lgam[cc];
        float4 vt = *(const float4*)&lbet[cc];
        float4 vm = *(const float4*)&lmean[cc];
        float4 vv = *(const float4*)&lvar[cc];
        float4 r;
        r.x = fmaxf((a.x + vb.x - vm.x) * (vg.x * rsqrtf(vv.x + BN_EPS)) + vt.x, 0.f);
        r.y = fmaxf((a.y + vb.y - vm.y) * (vg.y * rsqrtf(vv.y + BN_EPS)) + vt.y, 0.f);
        r.z = fmaxf((a.z + vb.z - vm.z) * (vg.z * rsqrtf(vv.z + BN_EPS)) + vt.z, 0.f);
        r.w = fmaxf((a.w + vb.w - vm.w) * (vg.w * rsqrtf(vv.w + BN_EPS)) + vt.w, 0.f);
        *(float4*)&g_cat[(size_t)nr*CM + cc] = r;
    }
}

// ---------------------------------------------------------------------------
// Kernel 4a: merge epilogue phase A — reduce partials, BN, ReLU; write
// unscaled y to out; per-(n,tile) squared sums to g_ss.
// grid = (4 tiles, 64 n) x 256 threads; 512 cols per block (2 per thread).
// ---------------------------------------------------------------------------
__global__ __launch_bounds__(256) void epi_mergeA(
    const float* __restrict__ mb,   const float* __restrict__ mgam,
    const float* __restrict__ mbet, const float* __restrict__ mmean,
    const float* __restrict__ mvar, float* __restrict__ out)
{
    int tile = blockIdx.x, nrow = blockIdx.y;
    int tid  = threadIdx.x, lane = tid & 31, warp = tid >> 5;
    int c = tile*512 + tid*2;

    float2 a = make_float2(0.f, 0.f);
    #pragma unroll
    for (int ks = 0; ks < KSM; ++ks) {
        float2 t = *(const float2*)&g_mpart[((size_t)ks*NN + nrow)*CC + c];
        a.x += t.x; a.y += t.y;
    }
    float2 vb = *(const float2*)&mb[c];
    float2 vg = *(const float2*)&mgam[c];
    float2 vt = *(const float2*)&mbet[c];
    float2 vm = *(const float2*)&mmean[c];
    float2 vv = *(const float2*)&mvar[c];
    float y0 = fmaxf((a.x + vb.x - vm.x) * (vg.x * rsqrtf(vv.x + BN_EPS)) + vt.x, 0.f);
    float y1 = fmaxf((a.y + vb.y - vm.y) * (vg.y * rsqrtf(vv.y + BN_EPS)) + vt.y, 0.f);
    *(float2*)&out[(size_t)nrow*CC + c] = make_float2(y0, y1);

    float ss = y0*y0 + y1*y1;
    #pragma unroll
    for (int o = 16; o > 0; o >>= 1)
        ss += __shfl_xor_sync(0xffffffffu, ss, o);
    __shared__ float sw[8];
    if (lane == 0) sw[warp] = ss;
    __syncthreads();
    if (tid == 0) {
        float t = 0.f;
        #pragma unroll
        for (int w = 0; w < 8; ++w) t += sw[w];
        g_ss[nrow*4 + tile] = t;
    }
}

// ---------------------------------------------------------------------------
// Kernel 4b: merge epilogue phase B — L2-normalize in place.
// grid = 64 x 256
// ---------------------------------------------------------------------------
__global__ __launch_bounds__(256) void epi_mergeB(float* __restrict__ out)
{
    int nrow = blockIdx.x, tid = threadIdx.x;
    float ssum = (g_ss[nrow*4+0] + g_ss[nrow*4+1]) + (g_ss[nrow*4+2] + g_ss[nrow*4+3]);
    float inv = 1.0f / fmaxf(sqrtf(ssum), 1e-12f);
    #pragma unroll
    for (int h = 0; h < 2; ++h) {
        size_t idx = (size_t)nrow*CC + h*1024 + tid*4;
        float4 v = *(float4*)&out[idx];
        v.x *= inv; v.y *= inv; v.z *= inv; v.w *= inv;
        *(float4*)&out[idx] = v;
    }
}

// ---------------------------------------------------------------------------
// Launch
// ---------------------------------------------------------------------------
extern "C" void kernel_launch(void* const* d_in, const int* in_sizes, int n_in,
                              void* d_out, int out_size)
{
    const float* x        = (const float*)d_in[0];
    const float* poses    = (const float*)d_in[1];
    const float* local_w  = (const float*)d_in[2];
    const float* local_b  = (const float*)d_in[3];
    const float* local_g  = (const float*)d_in[4];
    const float* local_be = (const float*)d_in[5];
    const float* local_m  = (const float*)d_in[6];
    const float* local_v  = (const float*)d_in[7];
    const float* merge_w  = (const float*)d_in[8];
    const float* merge_b  = (const float*)d_in[9];
    const float* merge_g  = (const float*)d_in[10];
    const float* merge_be = (const float*)d_in[11];
    const float* merge_m  = (const float*)d_in[12];
    const float* merge_v  = (const float*)d_in[13];
    float* out = (float*)d_out;

    cudaFuncSetAttribute(wgemm<0>, cudaFuncAttributeMaxDynamicSharedMemorySize, SMEMG);
    cudaFuncSetAttribute(wgemm<1>, cudaFuncAttributeMaxDynamicSharedMemorySize, SMEMG);

    pool_kernel<<<dim3(CC/256, NN), 256>>>(x, poses);
    wgemm<0><<<dim3(PC/128, KSL), 256, SMEMG>>>(local_w);
    epi_local<<<320, 256>>>(local_b, local_g, local_be, local_m, local_v);
    wgemm<1><<<dim3(CC/128, KSM), 256, SMEMG>>>(merge_w);
    epi_mergeA<<<dim3(4, NN), 256>>>(merge_b, merge_g, merge_be, merge_m, merge_v, out);
    epi_mergeB<<<NN, 256>>>(out);
}